// round 5
// baseline (speedup 1.0000x reference)
#include <cuda_runtime.h>
#include <cstddef>

// Problem constants
#define H      1024
#define BSZ    4
#define TLEN   1024
#define G4H    4096          // 4*H
#define NTOK   4096          // BSZ*TLEN
#define VOCAB  32000

// Recurrent kernel config
#define NCTA_R 128
#define TPB_R  256
#define UPC    8             // hidden units per CTA (H / NCTA_R)
#define RPC    32            // gate rows per CTA (4*UPC)
#define WPAD   1028          // padded row stride for Whh slice in smem

// Scratch (device globals; no allocations allowed)
__device__ float g_act[(size_t)NTOK * H];
__device__ float g_pre[(size_t)NTOK * G4H];
__device__ float g_hs0[(size_t)NTOK * H];
__device__ float g_hs1[(size_t)NTOK * H];
__device__ float g_h[BSZ * H];
__device__ int g_bar_count;              // always returns to 0 (deterministic across replays)
__device__ volatile int g_bar_flag;      // toggled an even # of times per launch -> returns to 0

// ---------------------------------------------------------------------------
// Embedding gather: out[n, :] = emb[x[n], :]
// ---------------------------------------------------------------------------
__global__ void embed_kernel(const int* __restrict__ x,
                             const float* __restrict__ emb,
                             float* __restrict__ out)
{
    int n = blockIdx.x;
    int tok = __ldg(&x[n]);
    const float4* src = (const float4*)(emb + (size_t)tok * H);
    float4* dst = (float4*)(out + (size_t)n * H);
    dst[threadIdx.x] = __ldg(&src[threadIdx.x]);
}

// ---------------------------------------------------------------------------
// SGEMM: C[M,N] = A[M,K] * B[N,K]^T + bias1[N] (+ bias2[N])
// Both A and B are row-major with K contiguous. M,N multiples of 128, K of 16.
// 128x128 tile, BK=16, 256 threads, 8x8 per thread (split 4+4 quadrants).
// ---------------------------------------------------------------------------
__global__ __launch_bounds__(256, 2)
void sgemm_abt(const float* __restrict__ A, const float* __restrict__ B,
               const float* __restrict__ bias1, const float* __restrict__ bias2,
               float* __restrict__ C, int M, int N, int K)
{
    __shared__ float As[16][132];
    __shared__ float Bs[16][132];
    const int tid = threadIdx.x;
    const int bm = blockIdx.y * 128;
    const int bn = blockIdx.x * 128;
    const int tx = tid & 15;
    const int ty = tid >> 4;
    const int lr = tid >> 2;          // 0..63
    const int lk = (tid & 3) << 2;    // 0,4,8,12

    const float* Ag = A + (size_t)(bm + lr) * K + lk;
    const float* Bg = B + (size_t)(bn + lr) * K + lk;

    float acc[8][8];
#pragma unroll
    for (int i = 0; i < 8; i++)
#pragma unroll
        for (int j = 0; j < 8; j++) acc[i][j] = 0.f;

    // register-prefetch first tile
    float4 a0 = *(const float4*)(Ag);
    float4 a1 = *(const float4*)(Ag + (size_t)64 * K);
    float4 b0 = *(const float4*)(Bg);
    float4 b1 = *(const float4*)(Bg + (size_t)64 * K);

    for (int k0 = 0; k0 < K; k0 += 16) {
        __syncthreads();
        As[lk+0][lr]    = a0.x; As[lk+1][lr]    = a0.y; As[lk+2][lr]    = a0.z; As[lk+3][lr]    = a0.w;
        As[lk+0][lr+64] = a1.x; As[lk+1][lr+64] = a1.y; As[lk+2][lr+64] = a1.z; As[lk+3][lr+64] = a1.w;
        Bs[lk+0][lr]    = b0.x; Bs[lk+1][lr]    = b0.y; Bs[lk+2][lr]    = b0.z; Bs[lk+3][lr]    = b0.w;
        Bs[lk+0][lr+64] = b1.x; Bs[lk+1][lr+64] = b1.y; Bs[lk+2][lr+64] = b1.z; Bs[lk+3][lr+64] = b1.w;
        __syncthreads();
        if (k0 + 16 < K) {      // prefetch next tile; latency hidden by compute below
            a0 = *(const float4*)(Ag + k0 + 16);
            a1 = *(const float4*)(Ag + (size_t)64 * K + k0 + 16);
            b0 = *(const float4*)(Bg + k0 + 16);
            b1 = *(const float4*)(Bg + (size_t)64 * K + k0 + 16);
        }
#pragma unroll
        for (int k = 0; k < 16; k++) {
            float4 aA = *(const float4*)&As[k][ty * 4];
            float4 aB = *(const float4*)&As[k][64 + ty * 4];
            float4 bA = *(const float4*)&Bs[k][tx * 4];
            float4 bB = *(const float4*)&Bs[k][64 + tx * 4];
            float av[8] = {aA.x, aA.y, aA.z, aA.w, aB.x, aB.y, aB.z, aB.w};
            float bv[8] = {bA.x, bA.y, bA.z, bA.w, bB.x, bB.y, bB.z, bB.w};
#pragma unroll
            for (int i = 0; i < 8; i++)
#pragma unroll
                for (int j = 0; j < 8; j++)
                    acc[i][j] += av[i] * bv[j];
        }
    }

    float bb[8];
#pragma unroll
    for (int jh = 0; jh < 2; jh++)
#pragma unroll
        for (int j = 0; j < 4; j++) {
            int n = bn + jh * 64 + tx * 4 + j;
            float v = bias1 ? __ldg(&bias1[n]) : 0.f;
            if (bias2) v += __ldg(&bias2[n]);
            bb[jh * 4 + j] = v;
        }
#pragma unroll
    for (int ih = 0; ih < 2; ih++)
#pragma unroll
        for (int i = 0; i < 4; i++) {
            int m = bm + ih * 64 + ty * 4 + i;
#pragma unroll
            for (int jh = 0; jh < 2; jh++) {
                float4 v;
                v.x = acc[ih*4+i][jh*4+0] + bb[jh*4+0];
                v.y = acc[ih*4+i][jh*4+1] + bb[jh*4+1];
                v.z = acc[ih*4+i][jh*4+2] + bb[jh*4+2];
                v.w = acc[ih*4+i][jh*4+3] + bb[jh*4+3];
                *(float4*)&C[(size_t)m * N + bn + jh * 64 + tx * 4] = v;
            }
        }
}

// ---------------------------------------------------------------------------
// Persistent LSTM recurrence. 128 CTAs (all resident), one CTA owns 8 hidden
// units = 32 gate rows of Whh, held in SMEM for all T steps. Grid-wide
// sense-reversing barrier between steps. State published through L2 (.cg).
// ---------------------------------------------------------------------------
__global__ __launch_bounds__(TPB_R)
void lstm_recurrent(const float* __restrict__ pre,
                    const float* __restrict__ Whh,
                    float* __restrict__ hs)
{
    extern __shared__ float sm[];
    float* whh_s = sm;                       // RPC * WPAD
    float* h_s   = sm + RPC * WPAD;          // BSZ * H
    float* z_s   = h_s + BSZ * H;            // RPC * BSZ
    float* c_s   = z_s + RPC * BSZ;          // 32

    const int tid  = threadIdx.x;
    const int cta  = blockIdx.x;
    const int warp = tid >> 5;
    const int lane = tid & 31;

    // Load Whh slice: local row r = q*8 + uu  -> global row q*H + cta*8 + uu
    for (int i = tid; i < RPC * H; i += TPB_R) {
        int r = i >> 10;
        int k = i & (H - 1);
        int q = r >> 3;
        int uu = r & 7;
        int grow = q * H + cta * UPC + uu;
        whh_s[r * WPAD + k] = __ldg(&Whh[(size_t)grow * H + k]);
    }
    if (tid < 32) c_s[tid] = 0.f;
    int sense = 0;
    __syncthreads();

    for (int t = 0; t < TLEN; t++) {
        // bring h(t-1) into smem (zeros at t=0); .cg to bypass stale L1
        float4* hs4 = (float4*)h_s;
        if (t == 0) {
            for (int i = tid; i < (BSZ * H) / 4; i += TPB_R)
                hs4[i] = make_float4(0.f, 0.f, 0.f, 0.f);
        } else {
            const float4* hg = (const float4*)g_h;
            for (int i = tid; i < (BSZ * H) / 4; i += TPB_R)
                hs4[i] = __ldcg(hg + i);
        }
        // prefetch pre-activations for gate threads (latency hidden by dots)
        float p0 = 0.f, p1 = 0.f, p2 = 0.f, p3 = 0.f;
        int uu = 0, b = 0;
        if (tid < 32) {
            uu = tid >> 2; b = tid & 3;
            size_t base = ((size_t)(b * TLEN + t)) * G4H + cta * UPC + uu;
            p0 = __ldg(&pre[base]);
            p1 = __ldg(&pre[base + H]);
            p2 = __ldg(&pre[base + 2 * H]);
            p3 = __ldg(&pre[base + 3 * H]);
        }
        __syncthreads();

        // z[r][b] = sum_k Whh_s[r][k] * h[b][k]; warp owns 4 rows, all 4 b.
        float acc[4][4];
#pragma unroll
        for (int i = 0; i < 4; i++)
#pragma unroll
            for (int j = 0; j < 4; j++) acc[i][j] = 0.f;

        const int rbase = warp * 4;
#pragma unroll
        for (int p = 0; p < 8; p++) {
            int k = p * 128 + lane * 4;
            float4 h0 = *(const float4*)&h_s[k];
            float4 h1 = *(const float4*)&h_s[H + k];
            float4 h2 = *(const float4*)&h_s[2 * H + k];
            float4 h3 = *(const float4*)&h_s[3 * H + k];
#pragma unroll
            for (int i = 0; i < 4; i++) {
                float4 w = *(const float4*)&whh_s[(rbase + i) * WPAD + k];
                acc[i][0] += w.x*h0.x + w.y*h0.y + w.z*h0.z + w.w*h0.w;
                acc[i][1] += w.x*h1.x + w.y*h1.y + w.z*h1.z + w.w*h1.w;
                acc[i][2] += w.x*h2.x + w.y*h2.y + w.z*h2.z + w.w*h2.w;
                acc[i][3] += w.x*h3.x + w.y*h3.y + w.z*h3.z + w.w*h3.w;
            }
        }
#pragma unroll
        for (int i = 0; i < 4; i++)
#pragma unroll
            for (int j = 0; j < 4; j++) {
                float v = acc[i][j];
                v += __shfl_xor_sync(0xffffffffu, v, 16);
                v += __shfl_xor_sync(0xffffffffu, v, 8);
                v += __shfl_xor_sync(0xffffffffu, v, 4);
                v += __shfl_xor_sync(0xffffffffu, v, 2);
                v += __shfl_xor_sync(0xffffffffu, v, 1);
                acc[i][j] = v;
            }
        if (lane == 0) {
#pragma unroll
            for (int i = 0; i < 4; i++)
#pragma unroll
                for (int j = 0; j < 4; j++)
                    z_s[(rbase + i) * 4 + j] = acc[i][j];
        }
        __syncthreads();

        // gates + state update (32 threads: uu x b)
        if (tid < 32) {
            float zi = z_s[uu * 4 + b] + p0;
            float zf = z_s[(8 + uu) * 4 + b] + p1;
            float zg = z_s[(16 + uu) * 4 + b] + p2;
            float zo = z_s[(24 + uu) * 4 + b] + p3;
            float ig = 1.f / (1.f + __expf(-zi));
            float fg = 1.f / (1.f + __expf(-zf));
            float gg = tanhf(zg);
            float og = 1.f / (1.f + __expf(-zo));
            float c = fg * c_s[tid] + ig * gg;
            c_s[tid] = c;
            float hval = og * tanhf(c);
            int col = cta * UPC + uu;
            __stcg(&g_h[b * H + col], hval);
            hs[((size_t)(b * TLEN + t)) * H + col] = hval;
        }
        __syncthreads();

        // grid-wide sense-reversing barrier (128 resident CTAs)
        if (tid == 0) {
            sense ^= 1;
            __threadfence();
            if (atomicAdd(&g_bar_count, 1) == NCTA_R - 1) {
                atomicExch(&g_bar_count, 0);
                __threadfence();
                g_bar_flag = sense;
            } else {
                while (g_bar_flag != sense) { }
            }
            __threadfence();
        }
        __syncthreads();
    }
}

// ---------------------------------------------------------------------------
// Host launcher (graph-capturable: kernels only)
// ---------------------------------------------------------------------------
extern "C" void kernel_launch(void* const* d_in, const int* in_sizes, int n_in,
                              void* d_out, int out_size)
{
    (void)in_sizes; (void)n_in; (void)out_size;
    const int*   x     = (const int*)  d_in[0];
    const float* emb   = (const float*)d_in[1];
    const float* Wproj = (const float*)d_in[2];
    const float* bproj = (const float*)d_in[3];
    const float* Wih0  = (const float*)d_in[4];
    const float* Whh0  = (const float*)d_in[5];
    const float* bih0  = (const float*)d_in[6];
    const float* bhh0  = (const float*)d_in[7];
    const float* Wih1  = (const float*)d_in[8];
    const float* Whh1  = (const float*)d_in[9];
    const float* bih1  = (const float*)d_in[10];
    const float* bhh1  = (const float*)d_in[11];
    float* out = (float*)d_out;

    float *act, *pre, *hs0, *hs1;
    cudaGetSymbolAddress((void**)&act, g_act);
    cudaGetSymbolAddress((void**)&pre, g_pre);
    cudaGetSymbolAddress((void**)&hs0, g_hs0);
    cudaGetSymbolAddress((void**)&hs1, g_hs1);

    const int RSMEM = (RPC * WPAD + BSZ * H + RPC * BSZ + 32) * 4;
    cudaFuncSetAttribute(lstm_recurrent,
                         cudaFuncAttributeMaxDynamicSharedMemorySize, RSMEM);

    // 1) embedding
    embed_kernel<<<NTOK, 256>>>(x, emb, act);

    // 2) layer 0: pre = act @ Wih0^T + bih0 + bhh0 ; recurrence
    dim3 g1(G4H / 128, NTOK / 128);
    sgemm_abt<<<g1, 256>>>(act, Wih0, bih0, bhh0, pre, NTOK, G4H, H);
    lstm_recurrent<<<NCTA_R, TPB_R, RSMEM>>>(pre, Whh0, hs0);

    // 3) layer 1
    sgemm_abt<<<g1, 256>>>(hs0, Wih1, bih1, bhh1, pre, NTOK, G4H, H);
    lstm_recurrent<<<NCTA_R, TPB_R, RSMEM>>>(pre, Whh1, hs1);

    // 4) projection: logits = hs1 @ Wproj^T + bproj
    dim3 g2(VOCAB / 128, NTOK / 128);
    sgemm_abt<<<g2, 256>>>(hs1, Wproj, bproj, nullptr, out, NTOK, VOCAB, H);
}

// round 6
// speedup vs baseline: 1.0437x; 1.0437x over previous
#include <cuda_runtime.h>
#include <cstddef>

// Problem constants
#define H      1024
#define BSZ    4
#define TLEN   1024
#define G4H    4096          // 4*H
#define NTOK   4096          // BSZ*TLEN
#define VOCAB  32000

// Recurrent kernel config
#define NCTA_R 128
#define TPB_R  256
#define UPC    8             // hidden units per CTA (H / NCTA_R)
#define RPC    32            // gate rows per CTA (4*UPC)
#define WPAD   1028          // padded row stride for Whh slice in smem

// Scratch (device globals; no allocations allowed)
__device__ float g_act[(size_t)NTOK * H];
__device__ float g_pre[(size_t)NTOK * G4H];
__device__ float g_hs0[(size_t)NTOK * H];
__device__ float g_hs1[(size_t)NTOK * H];
__device__ float g_h[BSZ * H];
__device__ int g_bar_count;   // returns to 0 every launch (deterministic replays)
__device__ int g_bar_flag;    // toggled an even # of times per launch -> returns to 0

// ---------------------------------------------------------------------------
// Packed fp32x2 helpers (FFMA2 — dual fp32 FMA per issue; PTX-only pattern)
// ---------------------------------------------------------------------------
__device__ __forceinline__ unsigned long long pk2(float x, float y) {
    unsigned long long r;
    asm("mov.b64 %0, {%1, %2};" : "=l"(r) : "f"(x), "f"(y));
    return r;
}
__device__ __forceinline__ void ffma2(unsigned long long& d,
                                      unsigned long long a,
                                      unsigned long long b) {
    asm("fma.rn.f32x2 %0, %1, %2, %0;" : "+l"(d) : "l"(a), "l"(b));
}
__device__ __forceinline__ float2 upk2(unsigned long long v) {
    float2 f;
    asm("mov.b64 {%0, %1}, %2;" : "=f"(f.x), "=f"(f.y) : "l"(v));
    return f;
}

// ---------------------------------------------------------------------------
// Embedding gather: out[n, :] = emb[x[n], :]
// ---------------------------------------------------------------------------
__global__ void embed_kernel(const int* __restrict__ x,
                             const float* __restrict__ emb,
                             float* __restrict__ out)
{
    int n = blockIdx.x;
    int tok = __ldg(&x[n]);
    const float4* src = (const float4*)(emb + (size_t)tok * H);
    float4* dst = (float4*)(out + (size_t)n * H);
    dst[threadIdx.x] = __ldg(&src[threadIdx.x]);
}

// ---------------------------------------------------------------------------
// SGEMM: C[M,N] = A[M,K] * B[N,K]^T + bias1[N] (+ bias2[N])
// 128x128 tile, BK=16, 256 threads, 8x8 per thread, FFMA2 inner loop
// (accumulators packed along the row dimension; a-pairs come free from
//  the float4 smem loads, only b needs 8 duplicate-MOVs per k on alu pipe).
// ---------------------------------------------------------------------------
__global__ __launch_bounds__(256, 2)
void sgemm_abt(const float* __restrict__ A, const float* __restrict__ B,
               const float* __restrict__ bias1, const float* __restrict__ bias2,
               float* __restrict__ C, int M, int N, int K)
{
    __shared__ float As[16][132];
    __shared__ float Bs[16][132];
    const int tid = threadIdx.x;
    const int bm = blockIdx.y * 128;
    const int bn = blockIdx.x * 128;
    const int tx = tid & 15;
    const int ty = tid >> 4;
    const int lr = tid >> 2;          // 0..63
    const int lk = (tid & 3) << 2;    // 0,4,8,12

    const float* Ag = A + (size_t)(bm + lr) * K + lk;
    const float* Bg = B + (size_t)(bn + lr) * K + lk;

    // acc2[i2][j]: packed pair of rows (2*i2, 2*i2+1) for column j
    unsigned long long acc2[4][8];
#pragma unroll
    for (int i = 0; i < 4; i++)
#pragma unroll
        for (int j = 0; j < 8; j++) acc2[i][j] = 0ull;

    // register-prefetch first tile
    float4 a0 = *(const float4*)(Ag);
    float4 a1 = *(const float4*)(Ag + (size_t)64 * K);
    float4 b0 = *(const float4*)(Bg);
    float4 b1 = *(const float4*)(Bg + (size_t)64 * K);

    for (int k0 = 0; k0 < K; k0 += 16) {
        __syncthreads();
        As[lk+0][lr]    = a0.x; As[lk+1][lr]    = a0.y; As[lk+2][lr]    = a0.z; As[lk+3][lr]    = a0.w;
        As[lk+0][lr+64] = a1.x; As[lk+1][lr+64] = a1.y; As[lk+2][lr+64] = a1.z; As[lk+3][lr+64] = a1.w;
        Bs[lk+0][lr]    = b0.x; Bs[lk+1][lr]    = b0.y; Bs[lk+2][lr]    = b0.z; Bs[lk+3][lr]    = b0.w;
        Bs[lk+0][lr+64] = b1.x; Bs[lk+1][lr+64] = b1.y; Bs[lk+2][lr+64] = b1.z; Bs[lk+3][lr+64] = b1.w;
        __syncthreads();
        if (k0 + 16 < K) {      // prefetch next tile; latency hidden by compute below
            a0 = *(const float4*)(Ag + k0 + 16);
            a1 = *(const float4*)(Ag + (size_t)64 * K + k0 + 16);
            b0 = *(const float4*)(Bg + k0 + 16);
            b1 = *(const float4*)(Bg + (size_t)64 * K + k0 + 16);
        }
#pragma unroll
        for (int k = 0; k < 16; k++) {
            float4 aA = *(const float4*)&As[k][ty * 4];
            float4 aB = *(const float4*)&As[k][64 + ty * 4];
            float4 bA = *(const float4*)&Bs[k][tx * 4];
            float4 bB = *(const float4*)&Bs[k][64 + tx * 4];
            unsigned long long av2[4];
            av2[0] = pk2(aA.x, aA.y);
            av2[1] = pk2(aA.z, aA.w);
            av2[2] = pk2(aB.x, aB.y);
            av2[3] = pk2(aB.z, aB.w);
            unsigned long long bv2[8];
            bv2[0] = pk2(bA.x, bA.x);
            bv2[1] = pk2(bA.y, bA.y);
            bv2[2] = pk2(bA.z, bA.z);
            bv2[3] = pk2(bA.w, bA.w);
            bv2[4] = pk2(bB.x, bB.x);
            bv2[5] = pk2(bB.y, bB.y);
            bv2[6] = pk2(bB.z, bB.z);
            bv2[7] = pk2(bB.w, bB.w);
#pragma unroll
            for (int i = 0; i < 4; i++)
#pragma unroll
                for (int j = 0; j < 8; j++)
                    ffma2(acc2[i][j], av2[i], bv2[j]);
        }
    }

    // unpack to scalar accumulators (epilogue only)
    float acc[8][8];
#pragma unroll
    for (int i2 = 0; i2 < 4; i2++)
#pragma unroll
        for (int j = 0; j < 8; j++) {
            float2 v = upk2(acc2[i2][j]);
            acc[2 * i2][j]     = v.x;
            acc[2 * i2 + 1][j] = v.y;
        }

    float bb[8];
#pragma unroll
    for (int jh = 0; jh < 2; jh++)
#pragma unroll
        for (int j = 0; j < 4; j++) {
            int n = bn + jh * 64 + tx * 4 + j;
            float v = bias1 ? __ldg(&bias1[n]) : 0.f;
            if (bias2) v += __ldg(&bias2[n]);
            bb[jh * 4 + j] = v;
        }
#pragma unroll
    for (int ih = 0; ih < 2; ih++)
#pragma unroll
        for (int i = 0; i < 4; i++) {
            int m = bm + ih * 64 + ty * 4 + i;
#pragma unroll
            for (int jh = 0; jh < 2; jh++) {
                float4 v;
                v.x = acc[ih*4+i][jh*4+0] + bb[jh*4+0];
                v.y = acc[ih*4+i][jh*4+1] + bb[jh*4+1];
                v.z = acc[ih*4+i][jh*4+2] + bb[jh*4+2];
                v.w = acc[ih*4+i][jh*4+3] + bb[jh*4+3];
                *(float4*)&C[(size_t)m * N + bn + jh * 64 + tx * 4] = v;
            }
        }
}

// ---------------------------------------------------------------------------
// Persistent LSTM recurrence. 128 CTAs (all resident), one CTA owns 8 hidden
// units = 32 gate rows of Whh, held in SMEM for all T steps. Grid-wide
// sense-reversing barrier between steps using acq_rel atomics + release/
// acquire flag ops (NO __threadfence -> no per-step MEMBAR/CCTL.IVALL).
// State published through L2 (.cg).
// ---------------------------------------------------------------------------
__global__ __launch_bounds__(TPB_R)
void lstm_recurrent(const float* __restrict__ pre,
                    const float* __restrict__ Whh,
                    float* __restrict__ hs)
{
    extern __shared__ float sm[];
    float* whh_s = sm;                       // RPC * WPAD
    float* h_s   = sm + RPC * WPAD;          // BSZ * H
    float* z_s   = h_s + BSZ * H;            // RPC * BSZ
    float* c_s   = z_s + RPC * BSZ;          // 32

    const int tid  = threadIdx.x;
    const int cta  = blockIdx.x;
    const int warp = tid >> 5;
    const int lane = tid & 31;

    // Load Whh slice: local row r = q*8 + uu  -> global row q*H + cta*8 + uu
    for (int i = tid; i < RPC * H; i += TPB_R) {
        int r = i >> 10;
        int k = i & (H - 1);
        int q = r >> 3;
        int uu = r & 7;
        int grow = q * H + cta * UPC + uu;
        whh_s[r * WPAD + k] = __ldg(&Whh[(size_t)grow * H + k]);
    }
    if (tid < 32) c_s[tid] = 0.f;
    int sense = 0;
    __syncthreads();

    for (int t = 0; t < TLEN; t++) {
        // bring h(t-1) into smem (zeros at t=0); .cg to bypass stale L1
        float4* hs4 = (float4*)h_s;
        if (t == 0) {
            for (int i = tid; i < (BSZ * H) / 4; i += TPB_R)
                hs4[i] = make_float4(0.f, 0.f, 0.f, 0.f);
        } else {
            const float4* hg = (const float4*)g_h;
            for (int i = tid; i < (BSZ * H) / 4; i += TPB_R)
                hs4[i] = __ldcg(hg + i);
        }
        // prefetch pre-activations for gate threads (latency hidden by dots)
        float p0 = 0.f, p1 = 0.f, p2 = 0.f, p3 = 0.f;
        int uu = 0, b = 0;
        if (tid < 32) {
            uu = tid >> 2; b = tid & 3;
            size_t base = ((size_t)(b * TLEN + t)) * G4H + cta * UPC + uu;
            p0 = __ldg(&pre[base]);
            p1 = __ldg(&pre[base + H]);
            p2 = __ldg(&pre[base + 2 * H]);
            p3 = __ldg(&pre[base + 3 * H]);
        }
        __syncthreads();

        // z[r][b] = sum_k Whh_s[r][k] * h[b][k]; warp owns 4 rows, all 4 b.
        float acc[4][4];
#pragma unroll
        for (int i = 0; i < 4; i++)
#pragma unroll
            for (int j = 0; j < 4; j++) acc[i][j] = 0.f;

        const int rbase = warp * 4;
#pragma unroll
        for (int p = 0; p < 8; p++) {
            int k = p * 128 + lane * 4;
            float4 h0 = *(const float4*)&h_s[k];
            float4 h1 = *(const float4*)&h_s[H + k];
            float4 h2 = *(const float4*)&h_s[2 * H + k];
            float4 h3 = *(const float4*)&h_s[3 * H + k];
#pragma unroll
            for (int i = 0; i < 4; i++) {
                float4 w = *(const float4*)&whh_s[(rbase + i) * WPAD + k];
                acc[i][0] += w.x*h0.x + w.y*h0.y + w.z*h0.z + w.w*h0.w;
                acc[i][1] += w.x*h1.x + w.y*h1.y + w.z*h1.z + w.w*h1.w;
                acc[i][2] += w.x*h2.x + w.y*h2.y + w.z*h2.z + w.w*h2.w;
                acc[i][3] += w.x*h3.x + w.y*h3.y + w.z*h3.z + w.w*h3.w;
            }
        }
#pragma unroll
        for (int i = 0; i < 4; i++)
#pragma unroll
            for (int j = 0; j < 4; j++) {
                float v = acc[i][j];
                v += __shfl_xor_sync(0xffffffffu, v, 16);
                v += __shfl_xor_sync(0xffffffffu, v, 8);
                v += __shfl_xor_sync(0xffffffffu, v, 4);
                v += __shfl_xor_sync(0xffffffffu, v, 2);
                v += __shfl_xor_sync(0xffffffffu, v, 1);
                acc[i][j] = v;
            }
        if (lane == 0) {
#pragma unroll
            for (int i = 0; i < 4; i++)
#pragma unroll
                for (int j = 0; j < 4; j++)
                    z_s[(rbase + i) * 4 + j] = acc[i][j];
        }
        __syncthreads();

        // gates + state update (32 threads: uu x b)
        if (tid < 32) {
            float zi = z_s[uu * 4 + b] + p0;
            float zf = z_s[(8 + uu) * 4 + b] + p1;
            float zg = z_s[(16 + uu) * 4 + b] + p2;
            float zo = z_s[(24 + uu) * 4 + b] + p3;
            float ig = 1.f / (1.f + __expf(-zi));
            float fg = 1.f / (1.f + __expf(-zf));
            float gg = tanhf(zg);
            float og = 1.f / (1.f + __expf(-zo));
            float c = fg * c_s[tid] + ig * gg;
            c_s[tid] = c;
            float hval = og * tanhf(c);
            int col = cta * UPC + uu;
            __stcg(&g_h[b * H + col], hval);
            hs[((size_t)(b * TLEN + t)) * H + col] = hval;
        }
        __syncthreads();

        // grid-wide sense-reversing barrier (128 resident CTAs).
        // acq_rel RMW on arrival orders this CTA's prior .cg stores into the
        // chain; the last arriver resets the counter (relaxed) and publishes
        // the flag with release; waiters poll with acquire loads.
        if (tid == 0) {
            sense ^= 1;
            int prev;
            asm volatile("atom.add.acq_rel.gpu.s32 %0, [%1], 1;"
                         : "=r"(prev) : "l"(&g_bar_count) : "memory");
            if (prev == NCTA_R - 1) {
                asm volatile("st.relaxed.gpu.s32 [%0], %1;"
                             :: "l"(&g_bar_count), "r"(0) : "memory");
                asm volatile("st.release.gpu.s32 [%0], %1;"
                             :: "l"(&g_bar_flag), "r"(sense) : "memory");
            } else {
                int f;
                do {
                    asm volatile("ld.acquire.gpu.s32 %0, [%1];"
                                 : "=r"(f) : "l"(&g_bar_flag) : "memory");
                } while (f != sense);
            }
        }
        __syncthreads();
    }
}

// ---------------------------------------------------------------------------
// Host launcher (graph-capturable: kernels only)
// ---------------------------------------------------------------------------
extern "C" void kernel_launch(void* const* d_in, const int* in_sizes, int n_in,
                              void* d_out, int out_size)
{
    (void)in_sizes; (void)n_in; (void)out_size;
    const int*   x     = (const int*)  d_in[0];
    const float* emb   = (const float*)d_in[1];
    const float* Wproj = (const float*)d_in[2];
    const float* bproj = (const float*)d_in[3];
    const float* Wih0  = (const float*)d_in[4];
    const float* Whh0  = (const float*)d_in[5];
    const float* bih0  = (const float*)d_in[6];
    const float* bhh0  = (const float*)d_in[7];
    const float* Wih1  = (const float*)d_in[8];
    const float* Whh1  = (const float*)d_in[9];
    const float* bih1  = (const float*)d_in[10];
    const float* bhh1  = (const float*)d_in[11];
    float* out = (float*)d_out;

    float *act, *pre, *hs0, *hs1;
    cudaGetSymbolAddress((void**)&act, g_act);
    cudaGetSymbolAddress((void**)&pre, g_pre);
    cudaGetSymbolAddress((void**)&hs0, g_hs0);
    cudaGetSymbolAddress((void**)&hs1, g_hs1);

    const int RSMEM = (RPC * WPAD + BSZ * H + RPC * BSZ + 32) * 4;
    cudaFuncSetAttribute(lstm_recurrent,
                         cudaFuncAttributeMaxDynamicSharedMemorySize, RSMEM);

    // 1) embedding
    embed_kernel<<<NTOK, 256>>>(x, emb, act);

    // 2) layer 0: pre = act @ Wih0^T + bih0 + bhh0 ; recurrence
    dim3 g1(G4H / 128, NTOK / 128);
    sgemm_abt<<<g1, 256>>>(act, Wih0, bih0, bhh0, pre, NTOK, G4H, H);
    lstm_recurrent<<<NCTA_R, TPB_R, RSMEM>>>(pre, Whh0, hs0);

    // 3) layer 1
    sgemm_abt<<<g1, 256>>>(hs0, Wih1, bih1, bhh1, pre, NTOK, G4H, H);
    lstm_recurrent<<<NCTA_R, TPB_R, RSMEM>>>(pre, Whh1, hs1);

    // 4) projection: logits = hs1 @ Wproj^T + bproj
    dim3 g2(VOCAB / 128, NTOK / 128);
    sgemm_abt<<<g2, 256>>>(hs1, Wproj, bproj, nullptr, out, NTOK, VOCAB, H);
}